// round 7
// baseline (speedup 1.0000x reference)
#include <cuda_runtime.h>
#include <cuda_fp16.h>
#include <math.h>
#include <stdint.h>

// ---------------- problem constants ----------------
#define NB1 8192
#define NB2 8192
#define ND  128

// ---------------- screen tiling ----------------
#define BM 128
#define BN 64
#define SPLITC 16
#define COLS_PER_CTA (NB2 / SPLITC)          // 512
#define TILES (COLS_PER_CTA / BN)            // 8

// candidate collection
#define CAP 16
#define DELTA 0.25f

// smem map: Ah 32KB | Bh ring 3 x 16KB | n2 2KB | rowmin 512B
#define SMEM_A 0
#define SMEM_B 32768
#define BSTAGE 16384
#define SMEM_N2 (SMEM_B + 3 * BSTAGE)        // 81920
#define SMEM_RMIN (SMEM_N2 + 2048)           // 83968
#define SMEM_BYTES (SMEM_RMIN + 512)         // 84480  (2 CTAs/SM)

#define SW128(o) ((o) ^ (((o) >> 3) & 0x70))

// ---------------- scratch globals ----------------
__device__ __align__(16) float  g_n1[NB1];
__device__ __align__(16) float  g_n2[NB2];
__device__ __align__(16) __half g_Ah[NB1 * ND];
__device__ __align__(16) __half g_Bh[NB2 * ND];
__device__ unsigned g_ccnt[NB1 * SPLITC];
__device__ __align__(16) float2 g_cand[(size_t)NB1 * SPLITC * CAP];

// ---------------- PTX helpers (portable sm_80-level only) ----------------
__device__ __forceinline__ uint32_t smem_u32(const void* p) {
    uint32_t a;
    asm("{ .reg .u64 t; cvta.to.shared.u64 t, %1; cvt.u32.u64 %0, t; }" : "=r"(a) : "l"(p));
    return a;
}
#define CP_ASYNC16(dst, src) \
    asm volatile("cp.async.cg.shared.global [%0], [%1], 16;" :: "r"(dst), "l"(src) : "memory")
#define CP_COMMIT() asm volatile("cp.async.commit_group;" ::: "memory")
#define CP_WAIT1()  asm volatile("cp.async.wait_group 1;" ::: "memory")

#define LDMATRIX_X4(r0, r1, r2, r3, addr) \
    asm volatile("ldmatrix.sync.aligned.m8n8.x4.shared.b16 {%0,%1,%2,%3}, [%4];" \
        : "=r"(r0), "=r"(r1), "=r"(r2), "=r"(r3) : "r"(addr))

#define MMA16816(acc, a, b0v, b1v) \
    asm volatile("mma.sync.aligned.m16n8k16.row.col.f32.f16.f16.f32 " \
        "{%0,%1,%2,%3}, {%4,%5,%6,%7}, {%8,%9}, {%0,%1,%2,%3};" \
        : "+f"((acc)[0]), "+f"((acc)[1]), "+f"((acc)[2]), "+f"((acc)[3]) \
        : "r"((a)[0]), "r"((a)[1]), "r"((a)[2]), "r"((a)[3]), "r"(b0v), "r"(b1v))

// monotone float <-> unsigned encoding (atomicMin over possibly-negative v)
__device__ __forceinline__ unsigned fenc(float f) {
    unsigned u = __float_as_uint(f);
    return (u & 0x80000000u) ? ~u : (u | 0x80000000u);
}
__device__ __forceinline__ float fdec(unsigned u) {
    return (u & 0x80000000u) ? __uint_as_float(u & 0x7FFFFFFFu)
                             : __uint_as_float(~u);
}

// ---------------------------------------------------------------------------
// Kernel 0: fp16 hi conversion + squared norms + zero candidate counters.
// ---------------------------------------------------------------------------
__global__ void prep_kernel(const float* __restrict__ d1,
                            const float* __restrict__ d2) {
    int gid  = blockIdx.x * blockDim.x + threadIdx.x;
    int warp = gid >> 5;
    int lane = threadIdx.x & 31;
    if (gid < NB1 * SPLITC) g_ccnt[gid] = 0;
    if (warp >= NB1 + NB2) return;
    bool isB = (warp >= NB1);
    int row = isB ? warp - NB1 : warp;
    const float* src = (isB ? d2 : d1) + (size_t)row * ND;
    float4 v = ((const float4*)src)[lane];

    float s = v.x * v.x + v.y * v.y + v.z * v.z + v.w * v.w;
    #pragma unroll
    for (int o = 16; o; o >>= 1) s += __shfl_xor_sync(0xffffffffu, s, o);
    if (lane == 0) {
        if (isB) g_n2[row] = s;
        else     g_n1[row] = s;
    }

    __half2 h01 = __halves2half2(__float2half_rn(v.x), __float2half_rn(v.y));
    __half2 h23 = __halves2half2(__float2half_rn(v.z), __float2half_rn(v.w));
    uint2 hp = make_uint2(*(uint32_t*)&h01, *(uint32_t*)&h23);
    ((uint2*)(isB ? g_Bh : g_Ah))[(size_t)row * 32 + lane] = hp;
}

// ---------------------------------------------------------------------------
// smem loaders (SW128-swizzled K-major tiles)
// ---------------------------------------------------------------------------
__device__ __forceinline__ void load_a_panel(uint32_t dstbase, int row0, int tid) {
    #pragma unroll
    for (int g = 0; g < 8; g++) {
        int idx = g * 256 + tid;
        int chunk = idx >> 10;
        int rem   = idx & 1023;
        int row   = rem >> 3;
        int gi    = rem & 7;
        const __half* src = g_Ah + (size_t)(row0 + row) * ND + chunk * 64 + gi * 8;
        CP_ASYNC16(dstbase + chunk * 16384 + SW128(row * 128 + gi * 16), src);
    }
}
__device__ __forceinline__ void load_b_stage(uint32_t dstbase, int col0, int tid) {
    #pragma unroll
    for (int g = 0; g < 4; g++) {
        int idx = g * 256 + tid;
        int chunk = idx >> 9;
        int rem   = idx & 511;
        int row   = rem >> 3;
        int gi    = rem & 7;
        const __half* src = g_Bh + (size_t)(col0 + row) * ND + chunk * 64 + gi * 8;
        CP_ASYNC16(dstbase + chunk * 8192 + SW128(row * 128 + gi * 16), src);
    }
}

// ---------------------------------------------------------------------------
// Kernel 1 (screen): hi-only mma.sync GEMM + lagging-threshold collection.
// One __syncthreads per tile; thresholds from register running min + stale
// smem row-min (conservative superset -> correctness preserved).
// ---------------------------------------------------------------------------
__global__ void __launch_bounds__(256, 2)
screen_kernel() {
    extern __shared__ char smem[];
    const uint32_t sbase = smem_u32(smem);
    const int tid  = threadIdx.x;
    const int lane = tid & 31;
    const int warp = tid >> 5;
    const int wrow = (warp >> 1) * 32;
    const int wcol = (warp & 1) * 32;
    const int rowBase = blockIdx.x * BM;
    const int split   = blockIdx.y;
    const int colBase = split * COLS_PER_CTA;

    const int a_rl   = lane & 15;
    const int a_koff = (lane >> 4) * 8;
    const int b_nl   = (lane & 7) + (lane >> 4) * 8;
    const int b_koff = ((lane >> 3) & 1) * 8;

    unsigned* rmin = (unsigned*)(smem + SMEM_RMIN);
    if (tid < BM) rmin[tid] = 0xFFFFFFFFu;

    // slot -> local row for this thread (s = m*2 + chalf)
    int rowloc[4];
    #pragma unroll
    for (int s = 0; s < 4; s++)
        rowloc[s] = wrow + (s >> 1) * 16 + (s & 1) * 8 + (lane >> 2);

    // ---- prologue: A panel + n2 + first two B stages ----
    load_a_panel(sbase + SMEM_A, rowBase, tid);
    if (tid < 128)
        CP_ASYNC16(sbase + SMEM_N2 + tid * 16, g_n2 + colBase + tid * 4);
    load_b_stage(sbase + SMEM_B + 0 * BSTAGE, colBase + 0 * BN, tid);
    CP_COMMIT();
    load_b_stage(sbase + SMEM_B + 1 * BSTAGE, colBase + 1 * BN, tid);
    CP_COMMIT();

    const float* n2s = (const float*)(smem + SMEM_N2);

    float rbest[4] = {3.4e38f, 3.4e38f, 3.4e38f, 3.4e38f};

    for (int i = 0; i < TILES; i++) {
        CP_WAIT1();
        __syncthreads();      // B(i) visible; stage (i-1)%3 consumed

        if (i + 2 < TILES)
            load_b_stage(sbase + SMEM_B + ((i + 2) % 3) * BSTAGE,
                         colBase + (i + 2) * BN, tid);
        CP_COMMIT();

        const uint32_t abase = sbase + SMEM_A;
        const uint32_t bbase = sbase + SMEM_B + (i % 3) * BSTAGE;

        float acc[2][4][4];
        #pragma unroll
        for (int m = 0; m < 2; m++)
            #pragma unroll
            for (int n = 0; n < 4; n++)
                #pragma unroll
                for (int c = 0; c < 4; c++) acc[m][n][c] = 0.0f;

        #pragma unroll
        for (int ks = 0; ks < 8; ks++) {
            uint32_t aH[2][4], bH[2][4];
            #pragma unroll
            for (int m = 0; m < 2; m++) {
                int row = wrow + m * 16 + a_rl;
                int kb  = ks * 16 + a_koff;
                uint32_t addr = abase + (kb >> 6) * 16384 + row * 128 +
                                (((kb & 63) * 2) ^ ((row & 7) << 4));
                LDMATRIX_X4(aH[m][0], aH[m][1], aH[m][2], aH[m][3], addr);
            }
            #pragma unroll
            for (int pr = 0; pr < 2; pr++) {
                int nrow = wcol + pr * 16 + b_nl;
                int kb   = ks * 16 + b_koff;
                uint32_t addr = bbase + (kb >> 6) * 8192 + nrow * 128 +
                                (((kb & 63) * 2) ^ ((nrow & 7) << 4));
                LDMATRIX_X4(bH[pr][0], bH[pr][1], bH[pr][2], bH[pr][3], addr);
            }
            #pragma unroll
            for (int m = 0; m < 2; m++) {
                MMA16816(acc[m][0], aH[m], bH[0][0], bH[0][1]);
                MMA16816(acc[m][1], aH[m], bH[0][2], bH[0][3]);
                MMA16816(acc[m][2], aH[m], bH[1][0], bH[1][1]);
                MMA16816(acc[m][3], aH[m], bH[1][2], bH[1][3]);
            }
        }

        // ---- epilogue: v = n2 - 2*dot; quad running min; lag-threshold collect
        const int cloc = i * BN + wcol;
        float n2v[8];
        #pragma unroll
        for (int n = 0; n < 4; n++) {
            n2v[n * 2]     = n2s[cloc + n * 8 + (lane & 3) * 2];
            n2v[n * 2 + 1] = n2s[cloc + n * 8 + (lane & 3) * 2 + 1];
        }

        float smin[4] = {3.4e38f, 3.4e38f, 3.4e38f, 3.4e38f};
        #pragma unroll
        for (int m = 0; m < 2; m++)
            #pragma unroll
            for (int n = 0; n < 4; n++)
                #pragma unroll
                for (int c = 0; c < 4; c++) {
                    float v = n2v[n * 2 + (c & 1)] - 2.0f * acc[m][n][c];
                    acc[m][n][c] = v;
                    int s = m * 2 + (c >> 1);
                    smin[s] = fminf(smin[s], v);
                }

        float thr[4];
        #pragma unroll
        for (int s = 0; s < 4; s++) {
            float v2 = smin[s];   // quad min (lanes sharing a row)
            v2 = fminf(v2, __shfl_xor_sync(0xffffffffu, v2, 1));
            v2 = fminf(v2, __shfl_xor_sync(0xffffffffu, v2, 2));
            rbest[s] = fminf(rbest[s], v2);
            if ((lane & 3) == 0)
                atomicMin(&rmin[rowloc[s]], fenc(v2));
            float stale = fdec(rmin[rowloc[s]]);   // >= true running min: safe
            thr[s] = fminf(rbest[s], stale) + DELTA;
        }

        const int c0 = colBase + i * BN + wcol;
        #pragma unroll
        for (int m = 0; m < 2; m++)
            #pragma unroll
            for (int n = 0; n < 4; n++)
                #pragma unroll
                for (int c = 0; c < 4; c++) {
                    int s = m * 2 + (c >> 1);
                    float v = acc[m][n][c];
                    if (v < thr[s]) {
                        int col = c0 + n * 8 + (lane & 3) * 2 + (c & 1);
                        int gr  = rowBase + rowloc[s];
                        unsigned slot = atomicAdd(&g_ccnt[gr * SPLITC + split], 1u);
                        if (slot < CAP)
                            g_cand[((size_t)gr * SPLITC + split) * CAP + slot] =
                                make_float2(v, __int_as_float(col));
                    }
                }
    }
}

// ---------------------------------------------------------------------------
// Kernel 2 (rescore): warp per row. Screened min over candidates, then exact
// fp32 rescore of survivors; overflowed splits -> exact brute-force fallback.
// ---------------------------------------------------------------------------
__global__ void rescore_kernel(const float* __restrict__ d1,
                               const float* __restrict__ d2,
                               float* __restrict__ out) {
    int warp = (blockIdx.x * blockDim.x + threadIdx.x) >> 5;
    int lane = threadIdx.x & 31;
    if (warp >= NB1) return;
    const int row = warp;

    float4 a4 = ((const float4*)(d1 + (size_t)row * ND))[lane];
    float n1r = g_n1[row];

    // phase 1: screened minimum over stored candidates
    float m = 3.4e38f;
    if (lane < SPLITC) {
        unsigned n = g_ccnt[row * SPLITC + lane];
        if (n > CAP) n = CAP;
        size_t base = ((size_t)row * SPLITC + lane) * CAP;
        for (unsigned k = 0; k < n; k++)
            m = fminf(m, g_cand[base + k].x);
    }
    #pragma unroll
    for (int o = 16; o; o >>= 1)
        m = fminf(m, __shfl_xor_sync(0xffffffffu, m, o));
    const float thr = m + DELTA;

    // phase 2: exact rescore
    float bv = 3.4e38f;
    int   bj = 0x7fffffff;
    for (int sp = 0; sp < SPLITC; sp++) {
        unsigned n = g_ccnt[row * SPLITC + sp];
        if (n <= CAP) {
            size_t base = ((size_t)row * SPLITC + sp) * CAP;
            for (unsigned k = 0; k < n; k++) {
                float2 cd = g_cand[base + k];      // uniform across warp
                if (cd.x <= thr) {
                    int j = __float_as_int(cd.y);
                    float4 b4 = ((const float4*)(d2 + (size_t)j * ND))[lane];
                    float d = a4.x * b4.x + a4.y * b4.y + a4.z * b4.z + a4.w * b4.w;
                    #pragma unroll
                    for (int o = 16; o; o >>= 1)
                        d += __shfl_xor_sync(0xffffffffu, d, o);
                    float v = n1r + g_n2[j] - 2.0f * d;
                    if (v < bv || (v == bv && j < bj)) { bv = v; bj = j; }
                }
            }
        } else {
            // overflow fallback (P ~ 0): exact scan of this split, lane-parallel
            for (int c = lane; c < COLS_PER_CTA; c += 32) {
                int j = sp * COLS_PER_CTA + c;
                const float* b = d2 + (size_t)j * ND;
                float d = 0.0f;
                #pragma unroll 4
                for (int k = 0; k < ND; k++)
                    d += d1[(size_t)row * ND + k] * b[k];
                float v = n1r + g_n2[j] - 2.0f * d;
                if (v < bv || (v == bv && j < bj)) { bv = v; bj = j; }
            }
        }
    }

    // final warp reduction (handles lane-divergent fallback results; for the
    // uniform candidate path all lanes agree, so this is a no-op)
    #pragma unroll
    for (int o = 16; o; o >>= 1) {
        float ov = __shfl_xor_sync(0xffffffffu, bv, o);
        int   oj = __shfl_xor_sync(0xffffffffu, bj, o);
        if (ov < bv || (ov == bv && oj < bj)) { bv = ov; bj = oj; }
    }

    if (lane == 0) {
        out[row] = sqrtf(fmaxf(bv, 0.0f));
        out[NB1 + 2 * row]     = (float)row;
        out[NB1 + 2 * row + 1] = (float)bj;
    }
}

// ---------------------------------------------------------------------------
extern "C" void kernel_launch(void* const* d_in, const int* in_sizes, int n_in,
                              void* d_out, int out_size) {
    const float* d1 = (const float*)d_in[0];
    const float* d2 = (const float*)d_in[1];
    float* out = (float*)d_out;

    cudaFuncSetAttribute(screen_kernel,
                         cudaFuncAttributeMaxDynamicSharedMemorySize, SMEM_BYTES);

    prep_kernel<<<(NB1 + NB2) / 8, 256>>>(d1, d2);
    screen_kernel<<<dim3(NB1 / BM, SPLITC), 256, SMEM_BYTES>>>();
    rescore_kernel<<<NB1 / 8, 256>>>(d1, d2, out);
}

// round 8
// speedup vs baseline: 1.3629x; 1.3629x over previous
#include <cuda_runtime.h>
#include <cuda_fp16.h>
#include <math.h>
#include <stdint.h>

// ---------------- problem constants ----------------
#define NB1 8192
#define NB2 8192
#define ND  128

// ---------------- match tiling ----------------
#define BM 128
#define BN 64                  // columns per B stage (subtile)
#define SPLITC 16
#define COLS_PER_CTA (NB2 / SPLITC)          // 512
#define OUTER (COLS_PER_CTA / (2 * BN))      // 4 iterations x 128 cols

// smem map: A 64KB | B ring 4 x 32KB | n2 2KB
#define SMEM_A 0
#define SMEM_B 65536
#define BSTAGE 32768
#define SMEM_N2 (SMEM_B + 4 * BSTAGE)        // 196608
#define SMEM_BYTES (SMEM_N2 + 2048)          // 198656

#define SW128(o) ((o) ^ (((o) >> 3) & 0x70))

// ---------------- scratch globals ----------------
__device__ __align__(16) float  g_n1[NB1];
__device__ __align__(16) float  g_n2[NB2];
__device__ __align__(16) __half g_Ah[NB1 * ND];
__device__ __align__(16) __half g_Al[NB1 * ND];
__device__ __align__(16) __half g_Bh[NB2 * ND];
__device__ __align__(16) __half g_Bl[NB2 * ND];
__device__ float g_pval[NB1 * SPLITC];
__device__ int   g_pidx[NB1 * SPLITC];

// ---------------- PTX helpers (portable sm_80-level only) ----------------
__device__ __forceinline__ uint32_t smem_u32(const void* p) {
    uint32_t a;
    asm("{ .reg .u64 t; cvta.to.shared.u64 t, %1; cvt.u32.u64 %0, t; }" : "=r"(a) : "l"(p));
    return a;
}
#define CP_ASYNC16(dst, src) \
    asm volatile("cp.async.cg.shared.global [%0], [%1], 16;" :: "r"(dst), "l"(src) : "memory")
#define CP_COMMIT() asm volatile("cp.async.commit_group;" ::: "memory")
#define CP_WAIT0()  asm volatile("cp.async.wait_group 0;" ::: "memory")

#define LDMATRIX_X4(r0, r1, r2, r3, addr) \
    asm volatile("ldmatrix.sync.aligned.m8n8.x4.shared.b16 {%0,%1,%2,%3}, [%4];" \
        : "=r"(r0), "=r"(r1), "=r"(r2), "=r"(r3) : "r"(addr))

#define MMA16816(acc, a, b0v, b1v) \
    asm volatile("mma.sync.aligned.m16n8k16.row.col.f32.f16.f16.f32 " \
        "{%0,%1,%2,%3}, {%4,%5,%6,%7}, {%8,%9}, {%0,%1,%2,%3};" \
        : "+f"((acc)[0]), "+f"((acc)[1]), "+f"((acc)[2]), "+f"((acc)[3]) \
        : "r"((a)[0]), "r"((a)[1]), "r"((a)[2]), "r"((a)[3]), "r"(b0v), "r"(b1v))

// ---------------------------------------------------------------------------
// Kernel 0 (fused): fp16 Dekker split + squared norms. One warp per row.
// ---------------------------------------------------------------------------
__global__ void prep_kernel(const float* __restrict__ d1,
                            const float* __restrict__ d2) {
    int warp = (blockIdx.x * blockDim.x + threadIdx.x) >> 5;
    int lane = threadIdx.x & 31;
    if (warp >= NB1 + NB2) return;
    bool isB = (warp >= NB1);
    int row = isB ? warp - NB1 : warp;
    const float* src = (isB ? d2 : d1) + (size_t)row * ND;
    float4 v = ((const float4*)src)[lane];

    float s = v.x * v.x + v.y * v.y + v.z * v.z + v.w * v.w;
    #pragma unroll
    for (int o = 16; o; o >>= 1) s += __shfl_xor_sync(0xffffffffu, s, o);
    if (lane == 0) {
        if (isB) g_n2[row] = s;
        else     g_n1[row] = s;
    }

    __half hx = __float2half_rn(v.x), hy = __float2half_rn(v.y);
    __half hz = __float2half_rn(v.z), hw = __float2half_rn(v.w);
    __half2 h01 = __halves2half2(hx, hy);
    __half2 h23 = __halves2half2(hz, hw);
    __half2 l01 = __halves2half2(__float2half_rn(v.x - __half2float(hx)),
                                 __float2half_rn(v.y - __half2float(hy)));
    __half2 l23 = __halves2half2(__float2half_rn(v.z - __half2float(hz)),
                                 __float2half_rn(v.w - __half2float(hw)));
    uint2 hp = make_uint2(*(uint32_t*)&h01, *(uint32_t*)&h23);
    uint2 lp = make_uint2(*(uint32_t*)&l01, *(uint32_t*)&l23);
    size_t j = (size_t)row * 32 + lane;
    ((uint2*)(isB ? g_Bh : g_Ah))[j] = hp;
    ((uint2*)(isB ? g_Bl : g_Al))[j] = lp;
}

// ---------------------------------------------------------------------------
// smem loaders (SW128-swizzled K-major tiles, 16B granules via cp.async)
// A: [half][kchunk 2][128 rows][128B]   B stage: [half][kchunk 2][64 rows][128B]
// ---------------------------------------------------------------------------
__device__ __forceinline__ void load_a_panel(uint32_t dstbase, int row0, int tid) {
    #pragma unroll
    for (int g = 0; g < 16; g++) {
        int idx = g * 256 + tid;
        int half_ = idx >> 11;
        int rem   = idx & 2047;
        int chunk = rem >> 10;
        int rem2  = rem & 1023;
        int row   = rem2 >> 3;
        int gi    = rem2 & 7;
        const __half* src = (half_ ? g_Al : g_Ah) +
                            (size_t)(row0 + row) * ND + chunk * 64 + gi * 8;
        uint32_t dst = dstbase + half_ * 32768 + chunk * 16384 +
                       SW128(row * 128 + gi * 16);
        CP_ASYNC16(dst, src);
    }
}
__device__ __forceinline__ void load_b_stage(uint32_t dstbase, int col0, int tid) {
    #pragma unroll
    for (int g = 0; g < 8; g++) {
        int idx = g * 256 + tid;
        int half_ = idx >> 10;
        int rem   = idx & 1023;
        int chunk = rem >> 9;
        int rem2  = rem & 511;
        int row   = rem2 >> 3;
        int gi    = rem2 & 7;
        const __half* src = (half_ ? g_Bl : g_Bh) +
                            (size_t)(col0 + row) * ND + chunk * 64 + gi * 8;
        uint32_t dst = dstbase + half_ * 16384 + chunk * 8192 +
                       SW128(row * 128 + gi * 16);
        CP_ASYNC16(dst, src);
    }
}

// ---------------------------------------------------------------------------
// Kernel 1: mma.sync fp16x3 GEMM + fused argmin.
// 256 threads = 8 warps (4 row x 2 col); warp tile 32 rows x (32+32) cols.
// Each outer iteration consumes TWO 64-col B stages (128 cols): A fragments
// are loaded once per k-step and reused across both subtiles.
// ---------------------------------------------------------------------------
__global__ void __launch_bounds__(256, 1)
match_kernel() {
    extern __shared__ char smem[];
    const uint32_t sbase = smem_u32(smem);
    const int tid  = threadIdx.x;
    const int lane = tid & 31;
    const int warp = tid >> 5;
    const int wrow = (warp >> 1) * 32;
    const int wcol = (warp & 1) * 32;
    const int rowBase = blockIdx.x * BM;
    const int split   = blockIdx.y;
    const int colBase = split * COLS_PER_CTA;

    const int a_rl   = lane & 15;
    const int a_koff = (lane >> 4) * 8;
    const int b_nl   = (lane & 7) + (lane >> 4) * 8;
    const int b_koff = ((lane >> 3) & 1) * 8;

    // ---- prologue: A panel + n2 + stages 0,1 ----
    load_a_panel(sbase + SMEM_A, rowBase, tid);
    if (tid < 128)
        CP_ASYNC16(sbase + SMEM_N2 + tid * 16, g_n2 + colBase + tid * 4);
    load_b_stage(sbase + SMEM_B + 0 * BSTAGE, colBase + 0 * BN, tid);
    CP_COMMIT();
    load_b_stage(sbase + SMEM_B + 1 * BSTAGE, colBase + 1 * BN, tid);
    CP_COMMIT();

    const float* n2s = (const float*)(smem + SMEM_N2);

    float best[4];
    int   bidx[4];
    #pragma unroll
    for (int s = 0; s < 4; s++) { best[s] = 3.4e38f; bidx[s] = 0; }

    for (int it = 0; it < OUTER; it++) {
        CP_WAIT0();            // this iteration's two stages resident
        __syncthreads();       // previous iteration's stages fully consumed

        // prefetch the next iteration's two stages into the freed slots
        if (it + 1 < OUTER) {
            load_b_stage(sbase + SMEM_B + (((it + 1) * 2) & 3) * BSTAGE,
                         colBase + (it + 1) * 2 * BN, tid);
            CP_COMMIT();
            load_b_stage(sbase + SMEM_B + (((it + 1) * 2 + 1) & 3) * BSTAGE,
                         colBase + ((it + 1) * 2 + 1) * BN, tid);
            CP_COMMIT();
        }

        const uint32_t abase = sbase + SMEM_A;
        const uint32_t bbase0 = sbase + SMEM_B + ((it * 2) & 3) * BSTAGE;
        const uint32_t bbase1 = sbase + SMEM_B + ((it * 2 + 1) & 3) * BSTAGE;

        float acc[2][2][4][4];     // [m][subtile][npair][c]
        #pragma unroll
        for (int m = 0; m < 2; m++)
            #pragma unroll
            for (int sub = 0; sub < 2; sub++)
                #pragma unroll
                for (int n = 0; n < 4; n++)
                    #pragma unroll
                    for (int c = 0; c < 4; c++) acc[m][sub][n][c] = 0.0f;

        #pragma unroll
        for (int ks = 0; ks < 8; ks++) {
            uint32_t aH[2][4], aL[2][4];
            #pragma unroll
            for (int m = 0; m < 2; m++) {
                int row = wrow + m * 16 + a_rl;
                int kb  = ks * 16 + a_koff;
                uint32_t addr = abase + (kb >> 6) * 16384 + row * 128 +
                                (((kb & 63) * 2) ^ ((row & 7) << 4));
                LDMATRIX_X4(aH[m][0], aH[m][1], aH[m][2], aH[m][3], addr);
                LDMATRIX_X4(aL[m][0], aL[m][1], aL[m][2], aL[m][3], addr + 32768);
            }
            #pragma unroll
            for (int sub = 0; sub < 2; sub++) {
                const uint32_t bbase = sub ? bbase1 : bbase0;
                uint32_t bH[2][4], bL[2][4];
                #pragma unroll
                for (int pr = 0; pr < 2; pr++) {
                    int nrow = wcol + pr * 16 + b_nl;
                    int kb   = ks * 16 + b_koff;
                    uint32_t addr = bbase + (kb >> 6) * 8192 + nrow * 128 +
                                    (((kb & 63) * 2) ^ ((nrow & 7) << 4));
                    LDMATRIX_X4(bH[pr][0], bH[pr][1], bH[pr][2], bH[pr][3], addr);
                    LDMATRIX_X4(bL[pr][0], bL[pr][1], bL[pr][2], bL[pr][3], addr + 16384);
                }
                #pragma unroll
                for (int m = 0; m < 2; m++) {
                    MMA16816(acc[m][sub][0], aH[m], bH[0][0], bH[0][1]);
                    MMA16816(acc[m][sub][1], aH[m], bH[0][2], bH[0][3]);
                    MMA16816(acc[m][sub][2], aH[m], bH[1][0], bH[1][1]);
                    MMA16816(acc[m][sub][3], aH[m], bH[1][2], bH[1][3]);
                    MMA16816(acc[m][sub][0], aH[m], bL[0][0], bL[0][1]);
                    MMA16816(acc[m][sub][1], aH[m], bL[0][2], bL[0][3]);
                    MMA16816(acc[m][sub][2], aH[m], bL[1][0], bL[1][1]);
                    MMA16816(acc[m][sub][3], aH[m], bL[1][2], bL[1][3]);
                    MMA16816(acc[m][sub][0], aL[m], bH[0][0], bH[0][1]);
                    MMA16816(acc[m][sub][1], aL[m], bH[0][2], bH[0][3]);
                    MMA16816(acc[m][sub][2], aL[m], bH[1][0], bH[1][1]);
                    MMA16816(acc[m][sub][3], aL[m], bH[1][2], bH[1][3]);
                }
            }
        }

        // ---- fused argmin epilogue (n2 from smem), both subtiles ----
        #pragma unroll
        for (int sub = 0; sub < 2; sub++) {
            const int cloc = it * 2 * BN + sub * BN + wcol;
            const int c0   = colBase + cloc;
            float n2v[8];
            #pragma unroll
            for (int n = 0; n < 4; n++) {
                n2v[n * 2]     = n2s[cloc + n * 8 + (lane & 3) * 2];
                n2v[n * 2 + 1] = n2s[cloc + n * 8 + (lane & 3) * 2 + 1];
            }
            #pragma unroll
            for (int m = 0; m < 2; m++)
                #pragma unroll
                for (int n = 0; n < 4; n++)
                    #pragma unroll
                    for (int c = 0; c < 4; c++) {
                        float v = n2v[n * 2 + (c & 1)] - 2.0f * acc[m][sub][n][c];
                        int col = c0 + n * 8 + (lane & 3) * 2 + (c & 1);
                        int s = m * 2 + (c >> 1);
                        if (v < best[s]) { best[s] = v; bidx[s] = col; }
                    }
        }
    }

    // ---- reduction: quad lanes share rows -> shfl, then 2 col-warps via smem
    __syncthreads();
    float* red_v = (float*)smem;
    int*   red_i = (int*)(smem + 1024);
    #pragma unroll
    for (int s = 0; s < 4; s++) {
        float bv = best[s];
        int   bi = bidx[s];
        #pragma unroll
        for (int off = 1; off <= 2; off <<= 1) {
            float ov = __shfl_xor_sync(0xffffffffu, bv, off);
            int   oi = __shfl_xor_sync(0xffffffffu, bi, off);
            if (ov < bv || (ov == bv && oi < bi)) { bv = ov; bi = oi; }
        }
        if ((lane & 3) == 0) {
            int row = wrow + (s >> 1) * 16 + (s & 1) * 8 + (lane >> 2);
            red_v[row * 2 + (warp & 1)] = bv;
            red_i[row * 2 + (warp & 1)] = bi;
        }
    }
    __syncthreads();
    if (tid < BM) {
        float bv = red_v[tid * 2];
        int   bi = red_i[tid * 2];
        float ov = red_v[tid * 2 + 1];
        int   oi = red_i[tid * 2 + 1];
        if (ov < bv || (ov == bv && oi < bi)) { bv = ov; bi = oi; }
        g_pval[(rowBase + tid) * SPLITC + split] = bv;
        g_pidx[(rowBase + tid) * SPLITC + split] = bi;
    }
}

// ---------------------------------------------------------------------------
// Kernel 2: reduce SPLITC partials per row (warp per row), add n1, sqrt, write
// ---------------------------------------------------------------------------
__global__ void final_kernel(float* __restrict__ out) {
    int warp = (blockIdx.x * blockDim.x + threadIdx.x) >> 5;
    int lane = threadIdx.x & 31;
    if (warp >= NB1) return;
    float bv = 3.4e38f;
    int   bi = 0x7fffffff;
    if (lane < SPLITC) {
        bv = g_pval[warp * SPLITC + lane];
        bi = g_pidx[warp * SPLITC + lane];
    }
    #pragma unroll
    for (int off = 8; off; off >>= 1) {
        float ov = __shfl_xor_sync(0xffffffffu, bv, off);
        int   oi = __shfl_xor_sync(0xffffffffu, bi, off);
        if (ov < bv || (ov == bv && oi < bi)) { bv = ov; bi = oi; }
    }
    if (lane == 0) {
        float dm = g_n1[warp] + bv;
        out[warp] = sqrtf(fmaxf(dm, 0.0f));
        out[NB1 + 2 * warp]     = (float)warp;
        out[NB1 + 2 * warp + 1] = (float)bi;
    }
}

// ---------------------------------------------------------------------------
extern "C" void kernel_launch(void* const* d_in, const int* in_sizes, int n_in,
                              void* d_out, int out_size) {
    const float* d1 = (const float*)d_in[0];
    const float* d2 = (const float*)d_in[1];
    float* out = (float*)d_out;

    cudaFuncSetAttribute(match_kernel,
                         cudaFuncAttributeMaxDynamicSharedMemorySize, SMEM_BYTES);

    prep_kernel<<<(NB1 + NB2) / 8, 256>>>(d1, d2);
    match_kernel<<<dim3(NB1 / BM, SPLITC), 256, SMEM_BYTES>>>();
    final_kernel<<<NB1 / 8, 256>>>(out);
}

// round 9
// speedup vs baseline: 1.6274x; 1.1941x over previous
#include <cuda_runtime.h>
#include <cuda_fp16.h>
#include <math.h>
#include <stdint.h>

// ---------------- problem constants ----------------
#define NB1 8192
#define NB2 8192
#define ND  128

// ---------------- phase A tiling ----------------
#define BM 128
#define BN 64
#define SPLITC 16
#define COLS_PER_CTA (NB2 / SPLITC)          // 512
#define OUTER (COLS_PER_CTA / (2 * BN))      // 4 iterations x 128 cols

#define DELTA 2.0f

// smem map: Ah 32KB | Bh ring 4 x 16KB | n2 2KB
#define SMEM_A 0
#define SMEM_B 32768
#define BSTAGE 16384
#define SMEM_N2 (SMEM_B + 4 * BSTAGE)        // 98304
#define SMEM_BYTES (SMEM_N2 + 2048)          // 100352 (2 CTAs/SM)

#define SW128(o) ((o) ^ (((o) >> 3) & 0x70))

// ---------------- scratch globals ----------------
__device__ __align__(16) float  g_n1[NB1];
__device__ __align__(16) float  g_n2[NB2];
__device__ __align__(16) __half g_Ah[NB1 * ND];
__device__ __align__(16) __half g_Bh[NB2 * ND];
__device__ __align__(16) __half g_vbuf[(size_t)NB1 * NB2];   // 128MB screen values

// ---------------- PTX helpers (portable sm_80-level only) ----------------
__device__ __forceinline__ uint32_t smem_u32(const void* p) {
    uint32_t a;
    asm("{ .reg .u64 t; cvta.to.shared.u64 t, %1; cvt.u32.u64 %0, t; }" : "=r"(a) : "l"(p));
    return a;
}
#define CP_ASYNC16(dst, src) \
    asm volatile("cp.async.cg.shared.global [%0], [%1], 16;" :: "r"(dst), "l"(src) : "memory")
#define CP_COMMIT() asm volatile("cp.async.commit_group;" ::: "memory")
#define CP_WAIT0()  asm volatile("cp.async.wait_group 0;" ::: "memory")

#define LDMATRIX_X4(r0, r1, r2, r3, addr) \
    asm volatile("ldmatrix.sync.aligned.m8n8.x4.shared.b16 {%0,%1,%2,%3}, [%4];" \
        : "=r"(r0), "=r"(r1), "=r"(r2), "=r"(r3) : "r"(addr))

#define MMA16816(acc, a, b0v, b1v) \
    asm volatile("mma.sync.aligned.m16n8k16.row.col.f32.f16.f16.f32 " \
        "{%0,%1,%2,%3}, {%4,%5,%6,%7}, {%8,%9}, {%0,%1,%2,%3};" \
        : "+f"((acc)[0]), "+f"((acc)[1]), "+f"((acc)[2]), "+f"((acc)[3]) \
        : "r"((a)[0]), "r"((a)[1]), "r"((a)[2]), "r"((a)[3]), "r"(b0v), "r"(b1v))

// ---------------------------------------------------------------------------
// Kernel 0: fp16 hi conversion + squared norms. One warp per row.
// ---------------------------------------------------------------------------
__global__ void prep_kernel(const float* __restrict__ d1,
                            const float* __restrict__ d2) {
    int warp = (blockIdx.x * blockDim.x + threadIdx.x) >> 5;
    int lane = threadIdx.x & 31;
    if (warp >= NB1 + NB2) return;
    bool isB = (warp >= NB1);
    int row = isB ? warp - NB1 : warp;
    const float* src = (isB ? d2 : d1) + (size_t)row * ND;
    float4 v = ((const float4*)src)[lane];

    float s = v.x * v.x + v.y * v.y + v.z * v.z + v.w * v.w;
    #pragma unroll
    for (int o = 16; o; o >>= 1) s += __shfl_xor_sync(0xffffffffu, s, o);
    if (lane == 0) {
        if (isB) g_n2[row] = s;
        else     g_n1[row] = s;
    }

    __half2 h01 = __halves2half2(__float2half_rn(v.x), __float2half_rn(v.y));
    __half2 h23 = __halves2half2(__float2half_rn(v.z), __float2half_rn(v.w));
    uint2 hp = make_uint2(*(uint32_t*)&h01, *(uint32_t*)&h23);
    ((uint2*)(isB ? g_Bh : g_Ah))[(size_t)row * 32 + lane] = hp;
}

// ---------------------------------------------------------------------------
// smem loaders (SW128-swizzled K-major hi tiles)
// A: [kchunk 2][128 rows][128B]   B stage: [kchunk 2][64 rows][128B]
// ---------------------------------------------------------------------------
__device__ __forceinline__ void load_a_panel(uint32_t dstbase, int row0, int tid) {
    #pragma unroll
    for (int g = 0; g < 8; g++) {
        int idx = g * 256 + tid;            // 2048 granules
        int chunk = idx >> 10;
        int rem   = idx & 1023;
        int row   = rem >> 3;
        int gi    = rem & 7;
        const __half* src = g_Ah + (size_t)(row0 + row) * ND + chunk * 64 + gi * 8;
        CP_ASYNC16(dstbase + chunk * 16384 + SW128(row * 128 + gi * 16), src);
    }
}
__device__ __forceinline__ void load_b_stage(uint32_t dstbase, int col0, int tid) {
    #pragma unroll
    for (int g = 0; g < 4; g++) {
        int idx = g * 256 + tid;            // 1024 granules
        int chunk = idx >> 9;
        int rem   = idx & 511;
        int row   = rem >> 3;
        int gi    = rem & 7;
        const __half* src = g_Bh + (size_t)(col0 + row) * ND + chunk * 64 + gi * 8;
        CP_ASYNC16(dstbase + chunk * 8192 + SW128(row * 128 + gi * 16), src);
    }
}

// ---------------------------------------------------------------------------
// Kernel 1 (phase A): hi-only mma.sync GEMM; epilogue converts v = n2 - 2*dot
// to fp16 and stores to g_vbuf in a PERMUTED layout (coalesced STG.128 only).
// Permutation within each row's 512-col split region:
//   p = split*512 + it*128 + (warp&1)*64 + sub*32 + (lane&3)*8 + n*2 + (c&1)
//   j = split*512 + it*128 + sub*64 + (warp&1)*32 + n*8 + (lane&3)*2 + (c&1)
// ---------------------------------------------------------------------------
__global__ void __launch_bounds__(256, 2)
screen_kernel() {
    extern __shared__ char smem[];
    const uint32_t sbase = smem_u32(smem);
    const int tid  = threadIdx.x;
    const int lane = tid & 31;
    const int warp = tid >> 5;
    const int wrow = (warp >> 1) * 32;
    const int wcol = (warp & 1) * 32;
    const int rowBase = blockIdx.x * BM;
    const int split   = blockIdx.y;
    const int colBase = split * COLS_PER_CTA;

    const int a_rl   = lane & 15;
    const int a_koff = (lane >> 4) * 8;
    const int b_nl   = (lane & 7) + (lane >> 4) * 8;
    const int b_koff = ((lane >> 3) & 1) * 8;

    // ---- prologue: A panel + n2 + stages 0,1 ----
    load_a_panel(sbase + SMEM_A, rowBase, tid);
    if (tid < 128)
        CP_ASYNC16(sbase + SMEM_N2 + tid * 16, g_n2 + colBase + tid * 4);
    load_b_stage(sbase + SMEM_B + 0 * BSTAGE, colBase + 0 * BN, tid);
    CP_COMMIT();
    load_b_stage(sbase + SMEM_B + 1 * BSTAGE, colBase + 1 * BN, tid);
    CP_COMMIT();

    const float* n2s = (const float*)(smem + SMEM_N2);

    for (int it = 0; it < OUTER; it++) {
        CP_WAIT0();
        __syncthreads();

        if (it + 1 < OUTER) {
            load_b_stage(sbase + SMEM_B + (((it + 1) * 2) & 3) * BSTAGE,
                         colBase + (it + 1) * 2 * BN, tid);
            CP_COMMIT();
            load_b_stage(sbase + SMEM_B + (((it + 1) * 2 + 1) & 3) * BSTAGE,
                         colBase + ((it + 1) * 2 + 1) * BN, tid);
            CP_COMMIT();
        }

        const uint32_t abase = sbase + SMEM_A;
        const uint32_t bbase0 = sbase + SMEM_B + ((it * 2) & 3) * BSTAGE;
        const uint32_t bbase1 = sbase + SMEM_B + ((it * 2 + 1) & 3) * BSTAGE;

        float acc[2][2][4][4];     // [m][subtile][npair][c]
        #pragma unroll
        for (int m = 0; m < 2; m++)
            #pragma unroll
            for (int sub = 0; sub < 2; sub++)
                #pragma unroll
                for (int n = 0; n < 4; n++)
                    #pragma unroll
                    for (int c = 0; c < 4; c++) acc[m][sub][n][c] = 0.0f;

        #pragma unroll
        for (int ks = 0; ks < 8; ks++) {
            uint32_t aH[2][4];
            #pragma unroll
            for (int m = 0; m < 2; m++) {
                int row = wrow + m * 16 + a_rl;
                int kb  = ks * 16 + a_koff;
                uint32_t addr = abase + (kb >> 6) * 16384 + row * 128 +
                                (((kb & 63) * 2) ^ ((row & 7) << 4));
                LDMATRIX_X4(aH[m][0], aH[m][1], aH[m][2], aH[m][3], addr);
            }
            #pragma unroll
            for (int sub = 0; sub < 2; sub++) {
                const uint32_t bbase = sub ? bbase1 : bbase0;
                uint32_t bH[2][4];
                #pragma unroll
                for (int pr = 0; pr < 2; pr++) {
                    int nrow = wcol + pr * 16 + b_nl;
                    int kb   = ks * 16 + b_koff;
                    uint32_t addr = bbase + (kb >> 6) * 8192 + nrow * 128 +
                                    (((kb & 63) * 2) ^ ((nrow & 7) << 4));
                    LDMATRIX_X4(bH[pr][0], bH[pr][1], bH[pr][2], bH[pr][3], addr);
                }
                #pragma unroll
                for (int m = 0; m < 2; m++) {
                    MMA16816(acc[m][sub][0], aH[m], bH[0][0], bH[0][1]);
                    MMA16816(acc[m][sub][1], aH[m], bH[0][2], bH[0][3]);
                    MMA16816(acc[m][sub][2], aH[m], bH[1][0], bH[1][1]);
                    MMA16816(acc[m][sub][3], aH[m], bH[1][2], bH[1][3]);
                }
            }
        }

        // ---- epilogue: fp16 convert + permuted coalesced stores ----
        #pragma unroll
        for (int sub = 0; sub < 2; sub++) {
            const int cloc = it * 128 + sub * 64 + wcol;
            float n2v[8];
            #pragma unroll
            for (int n = 0; n < 4; n++) {
                n2v[n * 2]     = n2s[cloc + n * 8 + (lane & 3) * 2];
                n2v[n * 2 + 1] = n2s[cloc + n * 8 + (lane & 3) * 2 + 1];
            }
            #pragma unroll
            for (int m = 0; m < 2; m++) {
                #pragma unroll
                for (int ch = 0; ch < 2; ch++) {
                    uint32_t h2[4];
                    #pragma unroll
                    for (int n = 0; n < 4; n++) {
                        float v0 = n2v[n * 2]     - 2.0f * acc[m][sub][n][ch * 2];
                        float v1 = n2v[n * 2 + 1] - 2.0f * acc[m][sub][n][ch * 2 + 1];
                        __half2 hh = __floats2half2_rn(v0, v1);
                        h2[n] = *(uint32_t*)&hh;
                    }
                    int grow = rowBase + wrow + m * 16 + ch * 8 + (lane >> 2);
                    size_t p = (size_t)grow * NB2 + split * 512 + it * 128 +
                               (warp & 1) * 64 + sub * 32 + (lane & 3) * 8;
                    *(uint4*)(g_vbuf + p) = make_uint4(h2[0], h2[1], h2[2], h2[3]);
                }
            }
        }
    }
}

// ---------------------------------------------------------------------------
// Kernel 2 (scan): warp per row. Pass 1: min of stored fp16 screen values.
// Pass 2: ballot candidates <= min + DELTA, exact fp32 rescore (first-index
// tie-break), write final outputs.
// ---------------------------------------------------------------------------
__global__ void scan_kernel(const float* __restrict__ d1,
                            const float* __restrict__ d2,
                            float* __restrict__ out) {
    int warp = (blockIdx.x * blockDim.x + threadIdx.x) >> 5;
    int lane = threadIdx.x & 31;
    if (warp >= NB1) return;
    const int row = warp;
    const uint4* vrow = (const uint4*)(g_vbuf + (size_t)row * NB2);

    // ---- pass 1: min over 8192 fp16 values (32 x uint4 per lane) ----
    __half2 mn2 = __floats2half2_rn(3.0e4f, 3.0e4f);
    #pragma unroll 4
    for (int it = 0; it < 32; it++) {
        uint4 q = vrow[it * 32 + lane];
        mn2 = __hmin2(mn2, *(__half2*)&q.x);
        mn2 = __hmin2(mn2, *(__half2*)&q.y);
        mn2 = __hmin2(mn2, *(__half2*)&q.z);
        mn2 = __hmin2(mn2, *(__half2*)&q.w);
    }
    float m = fminf(__low2float(mn2), __high2float(mn2));
    #pragma unroll
    for (int o = 16; o; o >>= 1)
        m = fminf(m, __shfl_xor_sync(0xffffffffu, m, o));
    const float thr = m + DELTA;

    // ---- pass 2: candidates + exact rescore ----
    float4 a4 = ((const float4*)(d1 + (size_t)row * ND))[lane];
    float n1r = g_n1[row];
    float bv = 3.4e38f;
    int   bj = 0x7fffffff;

    for (int it = 0; it < 32; it++) {
        uint4 q = vrow[it * 32 + lane];
        __half h[8];
        *(uint4*)h = q;
        #pragma unroll
        for (int k = 0; k < 8; k++) {
            bool f = (__half2float(h[k]) <= thr);
            unsigned bm = __ballot_sync(0xffffffffu, f);
            while (bm) {
                int src = __ffs(bm) - 1;
                bm &= bm - 1;
                int p = (it * 32 + src) * 8 + k;
                // inverse permutation: p -> column j
                int r7   = p & 127;
                int j    = (p & ~511) + ((p >> 7) & 3) * 128 +
                           ((r7 >> 5) & 1) * 64 + (r7 >> 6) * 32 +
                           ((r7 >> 1) & 3) * 8 + ((r7 >> 3) & 3) * 2 + (r7 & 1);
                float4 b4 = ((const float4*)(d2 + (size_t)j * ND))[lane];
                float d = a4.x * b4.x + a4.y * b4.y + a4.z * b4.z + a4.w * b4.w;
                #pragma unroll
                for (int o = 16; o; o >>= 1)
                    d += __shfl_xor_sync(0xffffffffu, d, o);
                float v = n1r + g_n2[j] - 2.0f * d;
                if (v < bv || (v == bv && j < bj)) { bv = v; bj = j; }
            }
        }
    }

    if (lane == 0) {
        out[row] = sqrtf(fmaxf(bv, 0.0f));
        out[NB1 + 2 * row]     = (float)row;
        out[NB1 + 2 * row + 1] = (float)bj;
    }
}

// ---------------------------------------------------------------------------
extern "C" void kernel_launch(void* const* d_in, const int* in_sizes, int n_in,
                              void* d_out, int out_size) {
    const float* d1 = (const float*)d_in[0];
    const float* d2 = (const float*)d_in[1];
    float* out = (float*)d_out;

    cudaFuncSetAttribute(screen_kernel,
                         cudaFuncAttributeMaxDynamicSharedMemorySize, SMEM_BYTES);

    prep_kernel<<<(NB1 + NB2) / 8, 256>>>(d1, d2);
    screen_kernel<<<dim3(NB1 / BM, SPLITC), 256, SMEM_BYTES>>>();
    scan_kernel<<<NB1 / 8, 256>>>(d1, d2, out);
}

// round 10
// speedup vs baseline: 1.9169x; 1.1779x over previous
#include <cuda_runtime.h>
#include <cuda_fp16.h>
#include <math.h>
#include <stdint.h>

// ---------------- problem constants ----------------
#define NB1 8192
#define NB2 8192
#define ND  128

// ---------------- phase A tiling ----------------
#define BM 128
#define BN 64
#define SPLITC 16
#define COLS_PER_CTA (NB2 / SPLITC)          // 512
#define OUTER (COLS_PER_CTA / (2 * BN))      // 4 iterations x 128 cols

// u8 quantization of screen values: u = clamp(round((v - QLO) / QSTEP))
#define QLO   (-64.0f)
#define QSTEP 1.5f
#define QINV  (1.0f / QSTEP)
#define THR_STEPS 3          // integer threshold margin (4.5 decoded; need >= 2.06)

// smem map: Ah 32KB | Bh ring 4 x 16KB | n2 2KB
#define SMEM_A 0
#define SMEM_B 32768
#define BSTAGE 16384
#define SMEM_N2 (SMEM_B + 4 * BSTAGE)        // 98304
#define SMEM_BYTES (SMEM_N2 + 2048)          // 100352 (2 CTAs/SM)

#define SW128(o) ((o) ^ (((o) >> 3) & 0x70))

// ---------------- scratch globals ----------------
__device__ __align__(16) float  g_n1[NB1];
__device__ __align__(16) float  g_n2[NB2];
__device__ __align__(16) __half g_Ah[NB1 * ND];
__device__ __align__(16) __half g_Bh[NB2 * ND];
__device__ __align__(16) uint8_t g_vbuf[(size_t)NB1 * NB2];   // 64MB u8 screen values

// ---------------- PTX helpers (portable sm_80-level only) ----------------
__device__ __forceinline__ uint32_t smem_u32(const void* p) {
    uint32_t a;
    asm("{ .reg .u64 t; cvta.to.shared.u64 t, %1; cvt.u32.u64 %0, t; }" : "=r"(a) : "l"(p));
    return a;
}
#define CP_ASYNC16(dst, src) \
    asm volatile("cp.async.cg.shared.global [%0], [%1], 16;" :: "r"(dst), "l"(src) : "memory")
#define CP_COMMIT() asm volatile("cp.async.commit_group;" ::: "memory")
#define CP_WAIT0()  asm volatile("cp.async.wait_group 0;" ::: "memory")

#define LDMATRIX_X4(r0, r1, r2, r3, addr) \
    asm volatile("ldmatrix.sync.aligned.m8n8.x4.shared.b16 {%0,%1,%2,%3}, [%4];" \
        : "=r"(r0), "=r"(r1), "=r"(r2), "=r"(r3) : "r"(addr))

#define MMA16816(acc, a, b0v, b1v) \
    asm volatile("mma.sync.aligned.m16n8k16.row.col.f32.f16.f16.f32 " \
        "{%0,%1,%2,%3}, {%4,%5,%6,%7}, {%8,%9}, {%0,%1,%2,%3};" \
        : "+f"((acc)[0]), "+f"((acc)[1]), "+f"((acc)[2]), "+f"((acc)[3]) \
        : "r"((a)[0]), "r"((a)[1]), "r"((a)[2]), "r"((a)[3]), "r"(b0v), "r"(b1v))

__device__ __forceinline__ uint32_t quant4(float v0, float v1, float v2, float v3) {
    int u0 = __float2int_rn((v0 - QLO) * QINV);
    int u1 = __float2int_rn((v1 - QLO) * QINV);
    int u2 = __float2int_rn((v2 - QLO) * QINV);
    int u3 = __float2int_rn((v3 - QLO) * QINV);
    u0 = min(max(u0, 0), 255); u1 = min(max(u1, 0), 255);
    u2 = min(max(u2, 0), 255); u3 = min(max(u3, 0), 255);
    return (uint32_t)u0 | ((uint32_t)u1 << 8) | ((uint32_t)u2 << 16) | ((uint32_t)u3 << 24);
}

// ---------------------------------------------------------------------------
// Kernel 0: fp16 hi conversion + squared norms. One warp per row.
// ---------------------------------------------------------------------------
__global__ void prep_kernel(const float* __restrict__ d1,
                            const float* __restrict__ d2) {
    int warp = (blockIdx.x * blockDim.x + threadIdx.x) >> 5;
    int lane = threadIdx.x & 31;
    if (warp >= NB1 + NB2) return;
    bool isB = (warp >= NB1);
    int row = isB ? warp - NB1 : warp;
    const float* src = (isB ? d2 : d1) + (size_t)row * ND;
    float4 v = ((const float4*)src)[lane];

    float s = v.x * v.x + v.y * v.y + v.z * v.z + v.w * v.w;
    #pragma unroll
    for (int o = 16; o; o >>= 1) s += __shfl_xor_sync(0xffffffffu, s, o);
    if (lane == 0) {
        if (isB) g_n2[row] = s;
        else     g_n1[row] = s;
    }

    __half2 h01 = __halves2half2(__float2half_rn(v.x), __float2half_rn(v.y));
    __half2 h23 = __halves2half2(__float2half_rn(v.z), __float2half_rn(v.w));
    uint2 hp = make_uint2(*(uint32_t*)&h01, *(uint32_t*)&h23);
    ((uint2*)(isB ? g_Bh : g_Ah))[(size_t)row * 32 + lane] = hp;
}

// ---------------------------------------------------------------------------
// smem loaders (SW128-swizzled K-major hi tiles)
// ---------------------------------------------------------------------------
__device__ __forceinline__ void load_a_panel(uint32_t dstbase, int row0, int tid) {
    #pragma unroll
    for (int g = 0; g < 8; g++) {
        int idx = g * 256 + tid;
        int chunk = idx >> 10;
        int rem   = idx & 1023;
        int row   = rem >> 3;
        int gi    = rem & 7;
        const __half* src = g_Ah + (size_t)(row0 + row) * ND + chunk * 64 + gi * 8;
        CP_ASYNC16(dstbase + chunk * 16384 + SW128(row * 128 + gi * 16), src);
    }
}
__device__ __forceinline__ void load_b_stage(uint32_t dstbase, int col0, int tid) {
    #pragma unroll
    for (int g = 0; g < 4; g++) {
        int idx = g * 256 + tid;
        int chunk = idx >> 9;
        int rem   = idx & 511;
        int row   = rem >> 3;
        int gi    = rem & 7;
        const __half* src = g_Bh + (size_t)(col0 + row) * ND + chunk * 64 + gi * 8;
        CP_ASYNC16(dstbase + chunk * 8192 + SW128(row * 128 + gi * 16), src);
    }
}

// ---------------------------------------------------------------------------
// Kernel 1 (screen): hi-only mma.sync GEMM; epilogue quantizes v = n2 - 2*dot
// to u8 and stores PERMUTED, one STG.128 (16 values) per (m, ch):
//   byte p (within the 128B iter-chunk) = w1*64 + l3*16 + sub*8 + n*2 + c
//   column j (within the chunk)         = sub*64 + w1*32 + n*8 + l3*2 + c
// ---------------------------------------------------------------------------
__global__ void __launch_bounds__(256, 2)
screen_kernel() {
    extern __shared__ char smem[];
    const uint32_t sbase = smem_u32(smem);
    const int tid  = threadIdx.x;
    const int lane = tid & 31;
    const int warp = tid >> 5;
    const int wrow = (warp >> 1) * 32;
    const int wcol = (warp & 1) * 32;
    const int rowBase = blockIdx.x * BM;
    const int split   = blockIdx.y;
    const int colBase = split * COLS_PER_CTA;

    const int a_rl   = lane & 15;
    const int a_koff = (lane >> 4) * 8;
    const int b_nl   = (lane & 7) + (lane >> 4) * 8;
    const int b_koff = ((lane >> 3) & 1) * 8;

    // ---- prologue: A panel + n2 + stages 0,1 ----
    load_a_panel(sbase + SMEM_A, rowBase, tid);
    if (tid < 128)
        CP_ASYNC16(sbase + SMEM_N2 + tid * 16, g_n2 + colBase + tid * 4);
    load_b_stage(sbase + SMEM_B + 0 * BSTAGE, colBase + 0 * BN, tid);
    CP_COMMIT();
    load_b_stage(sbase + SMEM_B + 1 * BSTAGE, colBase + 1 * BN, tid);
    CP_COMMIT();

    const float* n2s = (const float*)(smem + SMEM_N2);

    for (int it = 0; it < OUTER; it++) {
        CP_WAIT0();
        __syncthreads();

        if (it + 1 < OUTER) {
            load_b_stage(sbase + SMEM_B + (((it + 1) * 2) & 3) * BSTAGE,
                         colBase + (it + 1) * 2 * BN, tid);
            CP_COMMIT();
            load_b_stage(sbase + SMEM_B + (((it + 1) * 2 + 1) & 3) * BSTAGE,
                         colBase + ((it + 1) * 2 + 1) * BN, tid);
            CP_COMMIT();
        }

        const uint32_t abase = sbase + SMEM_A;
        const uint32_t bbase0 = sbase + SMEM_B + ((it * 2) & 3) * BSTAGE;
        const uint32_t bbase1 = sbase + SMEM_B + ((it * 2 + 1) & 3) * BSTAGE;

        float acc[2][2][4][4];     // [m][subtile][npair][c]
        #pragma unroll
        for (int m = 0; m < 2; m++)
            #pragma unroll
            for (int sub = 0; sub < 2; sub++)
                #pragma unroll
                for (int n = 0; n < 4; n++)
                    #pragma unroll
                    for (int c = 0; c < 4; c++) acc[m][sub][n][c] = 0.0f;

        #pragma unroll
        for (int ks = 0; ks < 8; ks++) {
            uint32_t aH[2][4];
            #pragma unroll
            for (int m = 0; m < 2; m++) {
                int row = wrow + m * 16 + a_rl;
                int kb  = ks * 16 + a_koff;
                uint32_t addr = abase + (kb >> 6) * 16384 + row * 128 +
                                (((kb & 63) * 2) ^ ((row & 7) << 4));
                LDMATRIX_X4(aH[m][0], aH[m][1], aH[m][2], aH[m][3], addr);
            }
            #pragma unroll
            for (int sub = 0; sub < 2; sub++) {
                const uint32_t bbase = sub ? bbase1 : bbase0;
                uint32_t bH[2][4];
                #pragma unroll
                for (int pr = 0; pr < 2; pr++) {
                    int nrow = wcol + pr * 16 + b_nl;
                    int kb   = ks * 16 + b_koff;
                    uint32_t addr = bbase + (kb >> 6) * 8192 + nrow * 128 +
                                    (((kb & 63) * 2) ^ ((nrow & 7) << 4));
                    LDMATRIX_X4(bH[pr][0], bH[pr][1], bH[pr][2], bH[pr][3], addr);
                }
                #pragma unroll
                for (int m = 0; m < 2; m++) {
                    MMA16816(acc[m][sub][0], aH[m], bH[0][0], bH[0][1]);
                    MMA16816(acc[m][sub][1], aH[m], bH[0][2], bH[0][3]);
                    MMA16816(acc[m][sub][2], aH[m], bH[1][0], bH[1][1]);
                    MMA16816(acc[m][sub][3], aH[m], bH[1][2], bH[1][3]);
                }
            }
        }

        // ---- epilogue: quantize to u8 + one STG.128 per (m, ch) ----
        // n2 values for both subtiles at this thread's column positions
        float n2v[2][8];
        #pragma unroll
        for (int sub = 0; sub < 2; sub++) {
            const int cloc = it * 128 + sub * 64 + wcol;
            #pragma unroll
            for (int n = 0; n < 4; n++) {
                n2v[sub][n * 2]     = n2s[cloc + n * 8 + (lane & 3) * 2];
                n2v[sub][n * 2 + 1] = n2s[cloc + n * 8 + (lane & 3) * 2 + 1];
            }
        }
        #pragma unroll
        for (int m = 0; m < 2; m++) {
            #pragma unroll
            for (int ch = 0; ch < 2; ch++) {
                uint32_t w[4];
                #pragma unroll
                for (int sub = 0; sub < 2; sub++) {
                    #pragma unroll
                    for (int np = 0; np < 2; np++) {   // n pairs (n = np*2, np*2+1)
                        int n0 = np * 2, n1 = np * 2 + 1;
                        w[sub * 2 + np] = quant4(
                            n2v[sub][n0 * 2]     - 2.0f * acc[m][sub][n0][ch * 2],
                            n2v[sub][n0 * 2 + 1] - 2.0f * acc[m][sub][n0][ch * 2 + 1],
                            n2v[sub][n1 * 2]     - 2.0f * acc[m][sub][n1][ch * 2],
                            n2v[sub][n1 * 2 + 1] - 2.0f * acc[m][sub][n1][ch * 2 + 1]);
                    }
                }
                int grow = rowBase + wrow + m * 16 + ch * 8 + (lane >> 2);
                size_t p = (size_t)grow * NB2 + split * 512 + it * 128 +
                           (warp & 1) * 64 + (lane & 3) * 16;
                *(uint4*)(g_vbuf + p) = make_uint4(w[0], w[1], w[2], w[3]);
            }
        }
    }
}

// ---------------------------------------------------------------------------
// Kernel 2 (scan): warp per row over 8192 u8 values (16 uint4 per lane).
// Pass 1: byte-SIMD min. Pass 2: candidates u <= umin + THR_STEPS, exact fp32
// rescore with first-index tie-break, write final outputs.
// ---------------------------------------------------------------------------
__global__ void scan_kernel(const float* __restrict__ d1,
                            const float* __restrict__ d2,
                            float* __restrict__ out) {
    int warp = (blockIdx.x * blockDim.x + threadIdx.x) >> 5;
    int lane = threadIdx.x & 31;
    if (warp >= NB1) return;
    const int row = warp;
    const uint4* vrow = (const uint4*)(g_vbuf + (size_t)row * NB2);  // 512 uint4

    // ---- pass 1: per-byte min ----
    uint32_t mn = 0xFFFFFFFFu;
    #pragma unroll 4
    for (int it = 0; it < 16; it++) {
        uint4 q = vrow[it * 32 + lane];
        mn = __vminu4(mn, q.x); mn = __vminu4(mn, q.y);
        mn = __vminu4(mn, q.z); mn = __vminu4(mn, q.w);
    }
    #pragma unroll
    for (int o = 16; o; o >>= 1)
        mn = __vminu4(mn, __shfl_xor_sync(0xffffffffu, mn, o));
    uint32_t umin = min(min(mn & 255u, (mn >> 8) & 255u),
                        min((mn >> 16) & 255u, (mn >> 24) & 255u));
    uint32_t uthr = min(umin + THR_STEPS, 255u);
    const uint32_t thr4 = uthr * 0x01010101u;

    // ---- pass 2: candidates + exact rescore (reads hit L2) ----
    float4 a4 = ((const float4*)(d1 + (size_t)row * ND))[lane];
    float n1r = g_n1[row];
    float bv = 3.4e38f;
    int   bj = 0x7fffffff;

    for (int it = 0; it < 16; it++) {
        uint4 q = vrow[it * 32 + lane];
        bool f = (__vcmpleu4(q.x, thr4) | __vcmpleu4(q.y, thr4) |
                  __vcmpleu4(q.z, thr4) | __vcmpleu4(q.w, thr4)) != 0u;
        unsigned bm = __ballot_sync(0xffffffffu, f);
        while (bm) {
            int src = __ffs(bm) - 1;
            bm &= bm - 1;
            uint32_t qs[4];
            qs[0] = __shfl_sync(0xffffffffu, q.x, src);
            qs[1] = __shfl_sync(0xffffffffu, q.y, src);
            qs[2] = __shfl_sync(0xffffffffu, q.z, src);
            qs[3] = __shfl_sync(0xffffffffu, q.w, src);
            #pragma unroll
            for (int wj = 0; wj < 4; wj++) {
                uint32_t cm = __vcmpleu4(qs[wj], thr4);
                while (cm) {
                    int bit = __ffs(cm) - 1;
                    cm &= ~(0xFFu << (bit & ~7));
                    int k = wj * 4 + (bit >> 3);
                    int p = (it * 32 + src) * 16 + k;
                    // inverse permutation: byte index p -> column j
                    int r7  = p & 127;
                    int w1  = r7 >> 6;
                    int l3  = (r7 >> 4) & 3;
                    int sub = (r7 >> 3) & 1;
                    int n   = (r7 >> 1) & 3;
                    int c   = r7 & 1;
                    int j = (p & ~127) + sub * 64 + w1 * 32 + n * 8 + l3 * 2 + c;
                    float4 b4 = ((const float4*)(d2 + (size_t)j * ND))[lane];
                    float d = a4.x * b4.x + a4.y * b4.y + a4.z * b4.z + a4.w * b4.w;
                    #pragma unroll
                    for (int o = 16; o; o >>= 1)
                        d += __shfl_xor_sync(0xffffffffu, d, o);
                    float v = n1r + g_n2[j] - 2.0f * d;
                    if (v < bv || (v == bv && j < bj)) { bv = v; bj = j; }
                }
            }
        }
    }

    if (lane == 0) {
        out[row] = sqrtf(fmaxf(bv, 0.0f));
        out[NB1 + 2 * row]     = (float)row;
        out[NB1 + 2 * row + 1] = (float)bj;
    }
}

// ---------------------------------------------------------------------------
extern "C" void kernel_launch(void* const* d_in, const int* in_sizes, int n_in,
                              void* d_out, int out_size) {
    const float* d1 = (const float*)d_in[0];
    const float* d2 = (const float*)d_in[1];
    float* out = (float*)d_out;

    cudaFuncSetAttribute(screen_kernel,
                         cudaFuncAttributeMaxDynamicSharedMemorySize, SMEM_BYTES);

    prep_kernel<<<(NB1 + NB2) / 8, 256>>>(d1, d2);
    screen_kernel<<<dim3(NB1 / BM, SPLITC), 256, SMEM_BYTES>>>();
    scan_kernel<<<NB1 / 8, 256>>>(d1, d2, out);
}

// round 11
// speedup vs baseline: 2.1126x; 1.1021x over previous
#include <cuda_runtime.h>
#include <cuda_fp16.h>
#include <math.h>
#include <stdint.h>

// ---------------- problem constants ----------------
#define NB1 8192
#define NB2 8192
#define ND  128

// ---------------- phase A tiling ----------------
#define BM 128
#define BN 64
#define SPLITC 16
#define COLS_PER_CTA (NB2 / SPLITC)          // 512
#define OUTER (COLS_PER_CTA / (2 * BN))      // 4 iterations x 128 cols

// u8 quantization of screen values: u = clamp(round((v - QLO) / QSTEP))
#define QLO   (-64.0f)
#define QSTEP 1.5f
#define QINV  (1.0f / QSTEP)
#define THR_STEPS 3          // integer threshold margin (4.5 decoded; need >= 2.06)

// smem map: Ah 32KB | Bh ring 4 x 16KB | n2 2KB
#define SMEM_A 0
#define SMEM_B 32768
#define BSTAGE 16384
#define SMEM_N2 (SMEM_B + 4 * BSTAGE)        // 98304
#define SMEM_BYTES (SMEM_N2 + 2048)          // 100352 (2 CTAs/SM)

#define SW128(o) ((o) ^ (((o) >> 3) & 0x70))

// ---------------- scratch globals ----------------
__device__ __align__(16) float  g_n1[NB1];
__device__ __align__(16) float  g_n2[NB2];
__device__ __align__(16) __half g_Ah[NB1 * ND];
__device__ __align__(16) __half g_Bh[NB2 * ND];
__device__ __align__(16) uint8_t g_vbuf[(size_t)NB1 * NB2];      // 64MB u8 screen values
__device__ __align__(16) uint8_t g_rmin[NB1 * SPLITC * 2];       // per (row, split, colwarp) min

// ---------------- PTX helpers (portable sm_80-level only) ----------------
__device__ __forceinline__ uint32_t smem_u32(const void* p) {
    uint32_t a;
    asm("{ .reg .u64 t; cvta.to.shared.u64 t, %1; cvt.u32.u64 %0, t; }" : "=r"(a) : "l"(p));
    return a;
}
#define CP_ASYNC16(dst, src) \
    asm volatile("cp.async.cg.shared.global [%0], [%1], 16;" :: "r"(dst), "l"(src) : "memory")
#define CP_COMMIT() asm volatile("cp.async.commit_group;" ::: "memory")
#define CP_WAIT0()  asm volatile("cp.async.wait_group 0;" ::: "memory")

#define LDMATRIX_X4(r0, r1, r2, r3, addr) \
    asm volatile("ldmatrix.sync.aligned.m8n8.x4.shared.b16 {%0,%1,%2,%3}, [%4];" \
        : "=r"(r0), "=r"(r1), "=r"(r2), "=r"(r3) : "r"(addr))

#define MMA16816(acc, a, b0v, b1v) \
    asm volatile("mma.sync.aligned.m16n8k16.row.col.f32.f16.f16.f32 " \
        "{%0,%1,%2,%3}, {%4,%5,%6,%7}, {%8,%9}, {%0,%1,%2,%3};" \
        : "+f"((acc)[0]), "+f"((acc)[1]), "+f"((acc)[2]), "+f"((acc)[3]) \
        : "r"((a)[0]), "r"((a)[1]), "r"((a)[2]), "r"((a)[3]), "r"(b0v), "r"(b1v))

__device__ __forceinline__ uint32_t quant4(float v0, float v1, float v2, float v3) {
    int u0 = __float2int_rn((v0 - QLO) * QINV);
    int u1 = __float2int_rn((v1 - QLO) * QINV);
    int u2 = __float2int_rn((v2 - QLO) * QINV);
    int u3 = __float2int_rn((v3 - QLO) * QINV);
    u0 = min(max(u0, 0), 255); u1 = min(max(u1, 0), 255);
    u2 = min(max(u2, 0), 255); u3 = min(max(u3, 0), 255);
    return (uint32_t)u0 | ((uint32_t)u1 << 8) | ((uint32_t)u2 << 16) | ((uint32_t)u3 << 24);
}

// ---------------------------------------------------------------------------
// Kernel 0: fp16 hi conversion + squared norms. One warp per row.
// ---------------------------------------------------------------------------
__global__ void prep_kernel(const float* __restrict__ d1,
                            const float* __restrict__ d2) {
    int warp = (blockIdx.x * blockDim.x + threadIdx.x) >> 5;
    int lane = threadIdx.x & 31;
    if (warp >= NB1 + NB2) return;
    bool isB = (warp >= NB1);
    int row = isB ? warp - NB1 : warp;
    const float* src = (isB ? d2 : d1) + (size_t)row * ND;
    float4 v = ((const float4*)src)[lane];

    float s = v.x * v.x + v.y * v.y + v.z * v.z + v.w * v.w;
    #pragma unroll
    for (int o = 16; o; o >>= 1) s += __shfl_xor_sync(0xffffffffu, s, o);
    if (lane == 0) {
        if (isB) g_n2[row] = s;
        else     g_n1[row] = s;
    }

    __half2 h01 = __halves2half2(__float2half_rn(v.x), __float2half_rn(v.y));
    __half2 h23 = __halves2half2(__float2half_rn(v.z), __float2half_rn(v.w));
    uint2 hp = make_uint2(*(uint32_t*)&h01, *(uint32_t*)&h23);
    ((uint2*)(isB ? g_Bh : g_Ah))[(size_t)row * 32 + lane] = hp;
}

// ---------------------------------------------------------------------------
// smem loaders (SW128-swizzled K-major hi tiles)
// ---------------------------------------------------------------------------
__device__ __forceinline__ void load_a_panel(uint32_t dstbase, int row0, int tid) {
    #pragma unroll
    for (int g = 0; g < 8; g++) {
        int idx = g * 256 + tid;
        int chunk = idx >> 10;
        int rem   = idx & 1023;
        int row   = rem >> 3;
        int gi    = rem & 7;
        const __half* src = g_Ah + (size_t)(row0 + row) * ND + chunk * 64 + gi * 8;
        CP_ASYNC16(dstbase + chunk * 16384 + SW128(row * 128 + gi * 16), src);
    }
}
__device__ __forceinline__ void load_b_stage(uint32_t dstbase, int col0, int tid) {
    #pragma unroll
    for (int g = 0; g < 4; g++) {
        int idx = g * 256 + tid;
        int chunk = idx >> 9;
        int rem   = idx & 511;
        int row   = rem >> 3;
        int gi    = rem & 7;
        const __half* src = g_Bh + (size_t)(col0 + row) * ND + chunk * 64 + gi * 8;
        CP_ASYNC16(dstbase + chunk * 8192 + SW128(row * 128 + gi * 16), src);
    }
}

// ---------------------------------------------------------------------------
// Kernel 1 (screen): hi-only mma.sync GEMM; epilogue quantizes v = n2 - 2*dot
// to u8, stores PERMUTED (one STG.128 per (m,ch)), and keeps a register
// running byte-min per (m,ch) row-slot. At kernel end the quad-reduced min is
// written once per (row, split, colwarp) -> scan needs NO min pass.
//   byte p (within the 128B iter-chunk) = w1*64 + l3*16 + sub*8 + n*2 + c
//   column j (within the chunk)         = sub*64 + w1*32 + n*8 + l3*2 + c
// ---------------------------------------------------------------------------
__global__ void __launch_bounds__(256, 2)
screen_kernel() {
    extern __shared__ char smem[];
    const uint32_t sbase = smem_u32(smem);
    const int tid  = threadIdx.x;
    const int lane = tid & 31;
    const int warp = tid >> 5;
    const int wrow = (warp >> 1) * 32;
    const int wcol = (warp & 1) * 32;
    const int rowBase = blockIdx.x * BM;
    const int split   = blockIdx.y;
    const int colBase = split * COLS_PER_CTA;

    const int a_rl   = lane & 15;
    const int a_koff = (lane >> 4) * 8;
    const int b_nl   = (lane & 7) + (lane >> 4) * 8;
    const int b_koff = ((lane >> 3) & 1) * 8;

    // ---- prologue: A panel + n2 + stages 0,1 ----
    load_a_panel(sbase + SMEM_A, rowBase, tid);
    if (tid < 128)
        CP_ASYNC16(sbase + SMEM_N2 + tid * 16, g_n2 + colBase + tid * 4);
    load_b_stage(sbase + SMEM_B + 0 * BSTAGE, colBase + 0 * BN, tid);
    CP_COMMIT();
    load_b_stage(sbase + SMEM_B + 1 * BSTAGE, colBase + 1 * BN, tid);
    CP_COMMIT();

    const float* n2s = (const float*)(smem + SMEM_N2);

    uint32_t rmin[2][2] = {{0xFFFFFFFFu, 0xFFFFFFFFu}, {0xFFFFFFFFu, 0xFFFFFFFFu}};

    for (int it = 0; it < OUTER; it++) {
        CP_WAIT0();
        __syncthreads();

        if (it + 1 < OUTER) {
            load_b_stage(sbase + SMEM_B + (((it + 1) * 2) & 3) * BSTAGE,
                         colBase + (it + 1) * 2 * BN, tid);
            CP_COMMIT();
            load_b_stage(sbase + SMEM_B + (((it + 1) * 2 + 1) & 3) * BSTAGE,
                         colBase + ((it + 1) * 2 + 1) * BN, tid);
            CP_COMMIT();
        }

        const uint32_t abase = sbase + SMEM_A;
        const uint32_t bbase0 = sbase + SMEM_B + ((it * 2) & 3) * BSTAGE;
        const uint32_t bbase1 = sbase + SMEM_B + ((it * 2 + 1) & 3) * BSTAGE;

        float acc[2][2][4][4];     // [m][subtile][npair][c]
        #pragma unroll
        for (int m = 0; m < 2; m++)
            #pragma unroll
            for (int sub = 0; sub < 2; sub++)
                #pragma unroll
                for (int n = 0; n < 4; n++)
                    #pragma unroll
                    for (int c = 0; c < 4; c++) acc[m][sub][n][c] = 0.0f;

        #pragma unroll
        for (int ks = 0; ks < 8; ks++) {
            uint32_t aH[2][4];
            #pragma unroll
            for (int m = 0; m < 2; m++) {
                int row = wrow + m * 16 + a_rl;
                int kb  = ks * 16 + a_koff;
                uint32_t addr = abase + (kb >> 6) * 16384 + row * 128 +
                                (((kb & 63) * 2) ^ ((row & 7) << 4));
                LDMATRIX_X4(aH[m][0], aH[m][1], aH[m][2], aH[m][3], addr);
            }
            #pragma unroll
            for (int sub = 0; sub < 2; sub++) {
                const uint32_t bbase = sub ? bbase1 : bbase0;
                uint32_t bH[2][4];
                #pragma unroll
                for (int pr = 0; pr < 2; pr++) {
                    int nrow = wcol + pr * 16 + b_nl;
                    int kb   = ks * 16 + b_koff;
                    uint32_t addr = bbase + (kb >> 6) * 8192 + nrow * 128 +
                                    (((kb & 63) * 2) ^ ((nrow & 7) << 4));
                    LDMATRIX_X4(bH[pr][0], bH[pr][1], bH[pr][2], bH[pr][3], addr);
                }
                #pragma unroll
                for (int m = 0; m < 2; m++) {
                    MMA16816(acc[m][sub][0], aH[m], bH[0][0], bH[0][1]);
                    MMA16816(acc[m][sub][1], aH[m], bH[0][2], bH[0][3]);
                    MMA16816(acc[m][sub][2], aH[m], bH[1][0], bH[1][1]);
                    MMA16816(acc[m][sub][3], aH[m], bH[1][2], bH[1][3]);
                }
            }
        }

        // ---- epilogue: quantize to u8, running min, one STG.128 per (m,ch) ----
        float n2v[2][8];
        #pragma unroll
        for (int sub = 0; sub < 2; sub++) {
            const int cloc = it * 128 + sub * 64 + wcol;
            #pragma unroll
            for (int n = 0; n < 4; n++) {
                n2v[sub][n * 2]     = n2s[cloc + n * 8 + (lane & 3) * 2];
                n2v[sub][n * 2 + 1] = n2s[cloc + n * 8 + (lane & 3) * 2 + 1];
            }
        }
        #pragma unroll
        for (int m = 0; m < 2; m++) {
            #pragma unroll
            for (int ch = 0; ch < 2; ch++) {
                uint32_t w[4];
                #pragma unroll
                for (int sub = 0; sub < 2; sub++) {
                    #pragma unroll
                    for (int np = 0; np < 2; np++) {
                        int n0 = np * 2, n1 = np * 2 + 1;
                        w[sub * 2 + np] = quant4(
                            n2v[sub][n0 * 2]     - 2.0f * acc[m][sub][n0][ch * 2],
                            n2v[sub][n0 * 2 + 1] - 2.0f * acc[m][sub][n0][ch * 2 + 1],
                            n2v[sub][n1 * 2]     - 2.0f * acc[m][sub][n1][ch * 2],
                            n2v[sub][n1 * 2 + 1] - 2.0f * acc[m][sub][n1][ch * 2 + 1]);
                    }
                }
                rmin[m][ch] = __vminu4(rmin[m][ch],
                              __vminu4(__vminu4(w[0], w[1]), __vminu4(w[2], w[3])));
                int grow = rowBase + wrow + m * 16 + ch * 8 + (lane >> 2);
                size_t p = (size_t)grow * NB2 + split * 512 + it * 128 +
                           (warp & 1) * 64 + (lane & 3) * 16;
                *(uint4*)(g_vbuf + p) = make_uint4(w[0], w[1], w[2], w[3]);
            }
        }
    }

    // ---- final: quad-reduce running mins, one byte store per row-slot ----
    #pragma unroll
    for (int m = 0; m < 2; m++)
        #pragma unroll
        for (int ch = 0; ch < 2; ch++) {
            uint32_t v = rmin[m][ch];
            v = __vminu4(v, __shfl_xor_sync(0xffffffffu, v, 1));
            v = __vminu4(v, __shfl_xor_sync(0xffffffffu, v, 2));
            uint32_t b = min(min(v & 255u, (v >> 8) & 255u),
                             min((v >> 16) & 255u, (v >> 24) & 255u));
            if ((lane & 3) == 0) {
                int grow = rowBase + wrow + m * 16 + ch * 8 + (lane >> 2);
                g_rmin[(grow * SPLITC + split) * 2 + (warp & 1)] = (uint8_t)b;
            }
        }
}

// ---------------------------------------------------------------------------
// Kernel 2 (scan): warp per row. Threshold from g_rmin (32 bytes), then ONE
// sweep over the row's 8192 u8 values: candidates u <= umin + THR_STEPS,
// exact fp32 rescore with first-index tie-break, write final outputs.
// ---------------------------------------------------------------------------
__global__ void scan_kernel(const float* __restrict__ d1,
                            const float* __restrict__ d2,
                            float* __restrict__ out) {
    int warp = (blockIdx.x * blockDim.x + threadIdx.x) >> 5;
    int lane = threadIdx.x & 31;
    if (warp >= NB1) return;
    const int row = warp;
    const uint4* vrow = (const uint4*)(g_vbuf + (size_t)row * NB2);  // 512 uint4

    // ---- threshold from precomputed per-split mins (32 bytes) ----
    uint32_t mn = 0xFFFFFFFFu;
    if (lane < 8)
        mn = ((const uint32_t*)(g_rmin + row * SPLITC * 2))[lane];
    #pragma unroll
    for (int o = 4; o; o >>= 1)
        mn = __vminu4(mn, __shfl_xor_sync(0xffffffffu, mn, o));
    mn = __shfl_sync(0xffffffffu, mn, 0);
    uint32_t umin = min(min(mn & 255u, (mn >> 8) & 255u),
                        min((mn >> 16) & 255u, (mn >> 24) & 255u));
    uint32_t uthr = min(umin + THR_STEPS, 255u);
    const uint32_t thr4 = uthr * 0x01010101u;

    // ---- single sweep: candidates + exact rescore ----
    float4 a4 = ((const float4*)(d1 + (size_t)row * ND))[lane];
    float n1r = g_n1[row];
    float bv = 3.4e38f;
    int   bj = 0x7fffffff;

    for (int it = 0; it < 16; it++) {
        uint4 q = vrow[it * 32 + lane];
        bool f = (__vcmpleu4(q.x, thr4) | __vcmpleu4(q.y, thr4) |
                  __vcmpleu4(q.z, thr4) | __vcmpleu4(q.w, thr4)) != 0u;
        unsigned bm = __ballot_sync(0xffffffffu, f);
        while (bm) {
            int src = __ffs(bm) - 1;
            bm &= bm - 1;
            uint32_t qs[4];
            qs[0] = __shfl_sync(0xffffffffu, q.x, src);
            qs[1] = __shfl_sync(0xffffffffu, q.y, src);
            qs[2] = __shfl_sync(0xffffffffu, q.z, src);
            qs[3] = __shfl_sync(0xffffffffu, q.w, src);
            #pragma unroll
            for (int wj = 0; wj < 4; wj++) {
                uint32_t cm = __vcmpleu4(qs[wj], thr4);
                while (cm) {
                    int bit = __ffs(cm) - 1;
                    cm &= ~(0xFFu << (bit & ~7));
                    int k = wj * 4 + (bit >> 3);
                    int p = (it * 32 + src) * 16 + k;
                    // inverse permutation: byte index p -> column j
                    int r7  = p & 127;
                    int w1  = r7 >> 6;
                    int l3  = (r7 >> 4) & 3;
                    int sub = (r7 >> 3) & 1;
                    int n   = (r7 >> 1) & 3;
                    int c   = r7 & 1;
                    int j = (p & ~127) + sub * 64 + w1 * 32 + n * 8 + l3 * 2 + c;
                    float4 b4 = ((const float4*)(d2 + (size_t)j * ND))[lane];
                    float d = a4.x * b4.x + a4.y * b4.y + a4.z * b4.z + a4.w * b4.w;
                    #pragma unroll
                    for (int o = 16; o; o >>= 1)
                        d += __shfl_xor_sync(0xffffffffu, d, o);
                    float v = n1r + g_n2[j] - 2.0f * d;
                    if (v < bv || (v == bv && j < bj)) { bv = v; bj = j; }
                }
            }
        }
    }

    if (lane == 0) {
        out[row] = sqrtf(fmaxf(bv, 0.0f));
        out[NB1 + 2 * row]     = (float)row;
        out[NB1 + 2 * row + 1] = (float)bj;
    }
}

// ---------------------------------------------------------------------------
extern "C" void kernel_launch(void* const* d_in, const int* in_sizes, int n_in,
                              void* d_out, int out_size) {
    const float* d1 = (const float*)d_in[0];
    const float* d2 = (const float*)d_in[1];
    float* out = (float*)d_out;

    cudaFuncSetAttribute(screen_kernel,
                         cudaFuncAttributeMaxDynamicSharedMemorySize, SMEM_BYTES);

    prep_kernel<<<(NB1 + NB2) / 8, 256>>>(d1, d2);
    screen_kernel<<<dim3(NB1 / BM, SPLITC), 256, SMEM_BYTES>>>();
    scan_kernel<<<NB1 / 8, 256>>>(d1, d2, out);
}